// round 14
// baseline (speedup 1.0000x reference)
#include <cuda_runtime.h>
#include <cuda_fp16.h>
#include <math.h>

#define BB 16
#define NN 512
#define HH 128
#define EE 4
#define NE 2048          /* NN*EE */
#define NR 8192          /* BB*NN */
#define STEPS 5

// ---------------- scratch (device globals; no allocation) ----------------
__device__ float g_h[NR * HH];
__device__ float g_ain[NR * HH];
__device__ float g_aout[NR * HH];
__device__ float g_z[NR * HH];
__device__ float g_rh[NR * HH];
// fp16 split planes: x = p0 + p1 (Dekker 2-way; residual <= 2^-24 |x|)
__device__ __half g_mA[2][BB][2][NN][NE];    // m planes [dir][b][p][n'][k]
__device__ __half g_stB[2][BB][2][NE][HH];   // state planes [dir][b][p][m'][h]

__device__ __forceinline__ float sigmoidf_(float v) { return 1.0f / (1.0f + expf(-v)); }

__device__ __forceinline__ void split2h(float x, __half& h0, __half& h1) {
  h0 = __float2half_rn(x);
  float r = x - __half2float(h0);
  h1 = __float2half_rn(r);
}

// ---------------- PTX helpers (all baseline sm_80+, legal on compute_103) ----
__device__ __forceinline__ void mma16(float (&d)[4], const unsigned (&a)[4],
                                      unsigned b0, unsigned b1) {
  asm volatile(
      "mma.sync.aligned.m16n8k16.row.col.f32.f16.f16.f32 "
      "{%0,%1,%2,%3}, {%4,%5,%6,%7}, {%8,%9}, {%0,%1,%2,%3};"
      : "+f"(d[0]), "+f"(d[1]), "+f"(d[2]), "+f"(d[3])
      : "r"(a[0]), "r"(a[1]), "r"(a[2]), "r"(a[3]), "r"(b0), "r"(b1));
}
__device__ __forceinline__ void ldm_x4(unsigned* r, unsigned addr) {
  asm volatile("ldmatrix.sync.aligned.m8n8.x4.shared.b16 {%0,%1,%2,%3}, [%4];"
               : "=r"(r[0]), "=r"(r[1]), "=r"(r[2]), "=r"(r[3]) : "r"(addr));
}
__device__ __forceinline__ void ldm_x4t(unsigned& r0, unsigned& r1, unsigned& r2,
                                        unsigned& r3, unsigned addr) {
  asm volatile("ldmatrix.sync.aligned.m8n8.x4.trans.shared.b16 {%0,%1,%2,%3}, [%4];"
               : "=r"(r0), "=r"(r1), "=r"(r2), "=r"(r3) : "r"(addr));
}
__device__ __forceinline__ void cpa16(unsigned dst, const void* src) {
  asm volatile("cp.async.cg.shared.global [%0], [%1], 16;" :: "r"(dst), "l"(src));
}
#define CP_COMMIT() asm volatile("cp.async.commit_group;" ::: "memory")
#define CP_WAIT0()  asm volatile("cp.async.wait_group 0;" ::: "memory")

// ---------------- one-time m split:  m -> 4 fp16 planes ----------------
__global__ void split_m_kernel(const float* __restrict__ mm) {
  long long i = (long long)blockIdx.x * 256 + threadIdx.x;   // over BB*NN*2*NE
  int j = (int)(i & 4095);
  long long bn = i >> 12;
  int n = (int)(bn & 511);
  int b = (int)(bn >> 9);
  int dir = j >> 11, k = j & 2047;
  float v = mm[i];
  __half p0, p1;
  split2h(v, p0, p1);
  g_mA[dir][b][0][n][k] = p0;
  g_mA[dir][b][1][n][k] = p1;
}

// ---------------- R2-proven fp32 SIMT GEMM core (proj/gates) ----------------
template <class ALoad, class BLoad, class Epi>
__device__ __forceinline__ void gemm64(ALoad aload, BLoad bload, Epi epi, int K) {
  __shared__ __align__(16) float As[16][68];
  __shared__ __align__(16) float Bs[16][64];
  float acc[4][4] = {};
  const int tid = threadIdx.x;
  const int tx = tid & 15, ty = tid >> 4;
  const int ar = tid >> 2, ak = (tid & 3) << 2;
  const int bk = tid >> 4, bn = (tid & 15) << 2;

  for (int k0 = 0; k0 < K; k0 += 16) {
    float4 av = aload(ar, k0 + ak);
    As[ak + 0][ar] = av.x;
    As[ak + 1][ar] = av.y;
    As[ak + 2][ar] = av.z;
    As[ak + 3][ar] = av.w;
    float4 bv = bload(k0 + bk, bn);
    *reinterpret_cast<float4*>(&Bs[bk][bn]) = bv;
    __syncthreads();
#pragma unroll
    for (int kk = 0; kk < 16; kk++) {
      float4 a4 = *reinterpret_cast<const float4*>(&As[kk][ty << 2]);
      float4 b4 = *reinterpret_cast<const float4*>(&Bs[kk][tx << 2]);
      float a[4] = {a4.x, a4.y, a4.z, a4.w};
      float b[4] = {b4.x, b4.y, b4.z, b4.w};
#pragma unroll
      for (int i = 0; i < 4; i++)
#pragma unroll
        for (int j = 0; j < 4; j++) acc[i][j] += a[i] * b[j];
    }
    __syncthreads();
  }
  epi(acc, ty, tx);
}

__global__ void copy_h_kernel(const float* __restrict__ x) {
  int i = blockIdx.x * 256 + threadIdx.x;
  g_h[i] = x[i];
}

// y = h @ W (+ bias) -> states written DIRECTLY as 2 fp16 planes
template <int DIR>
__global__ void proj_kernel(const float* __restrict__ W, const float* __restrict__ bias) {
  const int m0 = blockIdx.y << 6;
  const int n0 = blockIdx.x << 6;
  auto aload = [&](int r, int k) {
    return *reinterpret_cast<const float4*>(&g_h[(m0 + r) * HH + k]);
  };
  auto bload = [&](int k, int n) {
    return *reinterpret_cast<const float4*>(&W[k * (HH * EE) + n0 + n]);
  };
  auto epi = [&](float (&acc)[4][4], int ty, int tx) {
#pragma unroll
    for (int i = 0; i < 4; i++) {
      int row = m0 + (ty << 2) + i;
      int b = row >> 9, n = row & (NN - 1);
#pragma unroll
      for (int j = 0; j < 4; j++) {
        int col = n0 + (tx << 2) + j;
        int e = col & 3, hh = col >> 2;
        float v = acc[i][j] + bias[col];
        int mp = e * NN + n;
        __half p0, p1;
        split2h(v, p0, p1);
        g_stB[DIR][b][0][mp][hh] = p0;
        g_stB[DIR][b][1][mp][hh] = p1;
      }
    }
  };
  gemm64(aload, bload, epi, HH);
}

// ---------------- einsum: cp.async + ldmatrix + 4-term fp16 MMA ----------------
// K = 2048 in 32 chunks of 64. 2-stage cp.async ring, ONE sync per chunk.
// 8 warps (4M x 2N), warp tile 32x64, CTA tile 128x128.
// Per fragment group: two independent 2-deep MMA chains (p1 = A1B1+A1B0,
// p2 = A0B1+A0B0), each RN-folded into the master accumulator.
#define A_ROWB 144                     /* bytes per A smem row (128 data + 16 pad) */
#define A_PLB  (128 * A_ROWB)          /* 18432 B */
#define B_ROWB 272                     /* bytes per B smem k-row (256 + 16 pad) */
#define B_PLB  (64 * B_ROWB)           /* 17408 B */
#define A_STB  (2 * A_PLB)             /* 36864 B */
#define STAGE_B (A_STB + 2 * B_PLB)    /* 71680 B */
#define EIN_SMEM (2 * STAGE_B)         /* 143360 B */

__global__ __launch_bounds__(256, 1) void einsum_cp() {
  extern __shared__ __align__(16) char sm[];
  const unsigned su = (unsigned)__cvta_generic_to_shared(sm);
  const int tid = threadIdx.x, lane = tid & 31, wid = tid >> 5;
  const int wm = (wid & 3) << 5;     // warp M offset
  const int wn = (wid >> 2) << 6;    // warp N offset

  const int zz = blockIdx.y, dir = zz & 1, b = zz >> 1;
  const int m0 = blockIdx.x << 7;
  const __half* Ag = &g_mA[dir][b][0][0][0];   // plane stride NN*NE
  const __half* Bg = &g_stB[dir][b][0][0][0];  // plane stride NE*HH

  auto copy = [&](int c, int s) {
    const unsigned sb = su + s * STAGE_B;
#pragma unroll
    for (int i = 0; i < 8; i++) {            // A: 2 planes x 128 rows x 8 segs = 2048 x 16B
      int u = tid + (i << 8);
      int p = u >> 10, rem = u & 1023;
      int r = rem >> 3, seg = rem & 7;
      cpa16(sb + p * A_PLB + r * A_ROWB + seg * 16,
            Ag + (size_t)p * (NN * NE) + (size_t)(m0 + r) * NE + (c << 6) + seg * 8);
    }
#pragma unroll
    for (int i = 0; i < 8; i++) {            // B: 2 planes x 64 k-rows x 16 segs = 2048 x 16B
      int u = tid + (i << 8);
      int p = u >> 10, rem = u & 1023;
      int r = rem >> 4, seg = rem & 15;
      cpa16(sb + A_STB + p * B_PLB + r * B_ROWB + seg * 16,
            Bg + (size_t)p * (NE * HH) + (size_t)((c << 6) + r) * HH + seg * 8);
    }
  };

  float acc[2][8][4] = {};

  copy(0, 0); CP_COMMIT();

  const int la = lane & 7, lb = (lane >> 3) & 1, lc = lane >> 4;

  for (int c = 0; c < 32; c++) {
    CP_WAIT0();
    __syncthreads();                 // c's data visible; all warps done reading other stage
    if (c + 1 < 32) { copy(c + 1, (c + 1) & 1); CP_COMMIT(); }

    const unsigned Ab = su + (c & 1) * STAGE_B;
    const unsigned Bb = Ab + A_STB;
#pragma unroll
    for (int ks = 0; ks < 4; ks++) {
      unsigned af[2][2][4];
#pragma unroll
      for (int p = 0; p < 2; p++)
#pragma unroll
        for (int mi = 0; mi < 2; mi++)
          ldm_x4(af[p][mi],
                 Ab + p * A_PLB + (wm + (mi << 4) + la + lb * 8) * A_ROWB + ks * 32 + lc * 16);

      unsigned bfr[2][8][2];
#pragma unroll
      for (int p = 0; p < 2; p++)
#pragma unroll
        for (int g4 = 0; g4 < 4; g4++)
          ldm_x4t(bfr[p][2 * g4][0], bfr[p][2 * g4][1],
                  bfr[p][2 * g4 + 1][0], bfr[p][2 * g4 + 1][1],
                  Bb + p * B_PLB + ((ks << 4) + la + lb * 8) * B_ROWB +
                      (wn + (g4 << 4) + lc * 8) * 2);

#pragma unroll
      for (int nj = 0; nj < 8; nj++)
#pragma unroll
        for (int mi = 0; mi < 2; mi++) {
          float p1[4] = {0.f, 0.f, 0.f, 0.f};
          float p2[4] = {0.f, 0.f, 0.f, 0.f};
          mma16(p1, af[1][mi], bfr[1][nj][0], bfr[1][nj][1]);   // A1*B1
          mma16(p2, af[0][mi], bfr[1][nj][0], bfr[1][nj][1]);   // A0*B1
          mma16(p1, af[1][mi], bfr[0][nj][0], bfr[0][nj][1]);   // A1*B0
          mma16(p2, af[0][mi], bfr[0][nj][0], bfr[0][nj][1]);   // A0*B0
#pragma unroll
          for (int q = 0; q < 4; q++) acc[mi][nj][q] += p1[q];
#pragma unroll
          for (int q = 0; q < 4; q++) acc[mi][nj][q] += p2[q];
        }
    }
  }

  float* Cb = (dir ? g_aout : g_ain) + (size_t)(b * NN + m0) * HH;
  const int qr = lane >> 2, qc = lane & 3;
#pragma unroll
  for (int mi = 0; mi < 2; mi++)
#pragma unroll
    for (int nj = 0; nj < 8; nj++) {
      int r = wm + (mi << 4) + qr;
      int cc = wn + (nj << 3) + (qc << 1);
      *reinterpret_cast<float2*>(&Cb[r * HH + cc]) =
          make_float2(acc[mi][nj][0], acc[mi][nj][1]);
      *reinterpret_cast<float2*>(&Cb[(r + 8) * HH + cc]) =
          make_float2(acc[mi][nj][2], acc[mi][nj][3]);
    }
}

// Gate GEMMs (R2-proven SIMT)
template <int MODE>
__global__ void gate_kernel(const float* __restrict__ W, const float* __restrict__ bias) {
  const int m0 = blockIdx.y << 6;
  const int n0 = blockIdx.x << 6;
  const float* p3 = (MODE == 2) ? g_rh : g_h;
  auto aload = [&](int r, int k) -> float4 {
    int row = m0 + r;
    const float* base;
    if (k < 128)       base = &g_ain[row * HH + k];
    else if (k < 256)  base = &g_aout[row * HH + (k - 128)];
    else               base = &p3[row * HH + (k - 256)];
    return *reinterpret_cast<const float4*>(base);
  };
  auto bload = [&](int k, int n) {
    return *reinterpret_cast<const float4*>(&W[k * HH + n0 + n]);
  };
  auto epi = [&](float (&acc)[4][4], int ty, int tx) {
#pragma unroll
    for (int i = 0; i < 4; i++) {
      int row = m0 + (ty << 2) + i;
#pragma unroll
      for (int j = 0; j < 4; j++) {
        int col = n0 + (tx << 2) + j;
        float v = acc[i][j] + bias[col];
        int idx = row * HH + col;
        if (MODE == 0) {
          g_z[idx] = sigmoidf_(v);
        } else if (MODE == 1) {
          g_rh[idx] = sigmoidf_(v) * g_h[idx];
        } else {
          float t = tanhf(v);
          float z = g_z[idx];
          g_h[idx] = (1.0f - z) * g_h[idx] + z * t;
        }
      }
    }
  };
  gemm64(aload, bload, epi, 3 * HH);
}

__global__ void final_kernel(const float* __restrict__ a,
                             const float* __restrict__ W1,
                             const float* __restrict__ b1,
                             const float* __restrict__ W2,
                             const float* __restrict__ b2,
                             float* __restrict__ out) {
  const int row = blockIdx.x;
  const int j = threadIdx.x;
  __shared__ float sh[HH + 1];
  __shared__ float red[HH];
  sh[j] = g_h[row * HH + j];
  if (j == 0) sh[HH] = a[row];
  __syncthreads();
  float acc = b1[j];
#pragma unroll 4
  for (int k = 0; k < HH + 1; k++) acc += sh[k] * W1[k * HH + j];
  red[j] = tanhf(acc) * W2[j];
  __syncthreads();
  for (int s = 64; s > 0; s >>= 1) {
    if (j < s) red[j] += red[j + s];
    __syncthreads();
  }
  if (j == 0) out[row] = red[0] + b2[0];
}

// ---------------- launch ----------------
extern "C" void kernel_launch(void* const* d_in, const int* in_sizes, int n_in,
                              void* d_out, int out_size) {
  const float* x     = (const float*)d_in[0];
  const float* a     = (const float*)d_in[1];
  const float* m     = (const float*)d_in[2];
  const float* W_in  = (const float*)d_in[3];
  const float* b_in  = (const float*)d_in[4];
  const float* W_out = (const float*)d_in[5];
  const float* b_out = (const float*)d_in[6];
  const float* W_z   = (const float*)d_in[7];
  const float* b_z   = (const float*)d_in[8];
  const float* W_r   = (const float*)d_in[9];
  const float* b_r   = (const float*)d_in[10];
  const float* W_t   = (const float*)d_in[11];
  const float* b_t   = (const float*)d_in[12];
  const float* W1    = (const float*)d_in[13];
  const float* b1    = (const float*)d_in[14];
  const float* W2    = (const float*)d_in[15];
  const float* b2    = (const float*)d_in[16];
  float* out = (float*)d_out;

  cudaFuncSetAttribute(einsum_cp, cudaFuncAttributeMaxDynamicSharedMemorySize, EIN_SMEM);

  copy_h_kernel<<<NR * HH / 256, 256>>>(x);
  split_m_kernel<<<(BB * NN * 2 * NE) / 256, 256>>>(m);

  dim3 gp(8, 128);       // proj:   512/64 x 8192/64
  dim3 ge(4, 2 * BB);    // einsum: 512/128 x (b,dir)
  dim3 gg(2, 128);       // gates:  128/64 x 8192/64

  for (int s = 0; s < STEPS; s++) {
    proj_kernel<0><<<gp, 256>>>(W_in, b_in);
    proj_kernel<1><<<gp, 256>>>(W_out, b_out);
    einsum_cp<<<ge, 256, EIN_SMEM>>>();
    gate_kernel<0><<<gg, 256>>>(W_z, b_z);
    gate_kernel<1><<<gg, 256>>>(W_r, b_r);
    gate_kernel<2><<<gg, 256>>>(W_t, b_t);
  }

  final_kernel<<<NR, 128>>>(a, W1, b1, W2, b2, out);
}

// round 15
// speedup vs baseline: 1.3721x; 1.3721x over previous
#include <cuda_runtime.h>
#include <cuda_bf16.h>
#include <math.h>

#define BB 16
#define NN 512
#define HH 128
#define EE 4
#define NE 2048          /* NN*EE */
#define NR 8192          /* BB*NN */
#define STEPS 5

// ---------------- scratch (device globals; no allocation) ----------------
__device__ float g_h[NR * HH];
__device__ float g_ain[NR * HH];
__device__ float g_aout[NR * HH];
__device__ float g_z[NR * HH];
__device__ float g_rh[NR * HH];
// bf16 split planes: x = p0 + p1 + p2 (exact 3-way split)
__device__ __nv_bfloat16 g_mA[2][BB][3][NN][NE];    // m planes [dir][b][p][n'][k]
__device__ __nv_bfloat16 g_stB[2][BB][3][NE][HH];   // state planes [dir][b][p][m'][h]

__device__ __forceinline__ float sigmoidf_(float v) { return 1.0f / (1.0f + expf(-v)); }

__device__ __forceinline__ void split3b(float x, __nv_bfloat16& b0, __nv_bfloat16& b1,
                                        __nv_bfloat16& b2) {
  b0 = __float2bfloat16_rn(x);
  float r1 = x - __bfloat162float(b0);
  b1 = __float2bfloat16_rn(r1);
  float r2 = r1 - __bfloat162float(b1);
  b2 = __float2bfloat16_rn(r2);
}

// ---------------- PTX helpers (baseline sm_80+, legal on compute_103) ----
__device__ __forceinline__ void mma16(float (&d)[4], const unsigned (&a)[4],
                                      unsigned b0, unsigned b1) {
  asm volatile(
      "mma.sync.aligned.m16n8k16.row.col.f32.bf16.bf16.f32 "
      "{%0,%1,%2,%3}, {%4,%5,%6,%7}, {%8,%9}, {%0,%1,%2,%3};"
      : "+f"(d[0]), "+f"(d[1]), "+f"(d[2]), "+f"(d[3])
      : "r"(a[0]), "r"(a[1]), "r"(a[2]), "r"(a[3]), "r"(b0), "r"(b1));
}
__device__ __forceinline__ void ldm_x4(unsigned* r, unsigned addr) {
  asm volatile("ldmatrix.sync.aligned.m8n8.x4.shared.b16 {%0,%1,%2,%3}, [%4];"
               : "=r"(r[0]), "=r"(r[1]), "=r"(r[2]), "=r"(r[3]) : "r"(addr));
}
__device__ __forceinline__ void ldm_x4t(unsigned& r0, unsigned& r1, unsigned& r2,
                                        unsigned& r3, unsigned addr) {
  asm volatile("ldmatrix.sync.aligned.m8n8.x4.trans.shared.b16 {%0,%1,%2,%3}, [%4];"
               : "=r"(r0), "=r"(r1), "=r"(r2), "=r"(r3) : "r"(addr));
}
__device__ __forceinline__ void cpa16(unsigned dst, const void* src) {
  asm volatile("cp.async.cg.shared.global [%0], [%1], 16;" :: "r"(dst), "l"(src));
}
#define CP_COMMIT() asm volatile("cp.async.commit_group;" ::: "memory")
#define CP_WAIT0()  asm volatile("cp.async.wait_group 0;" ::: "memory")

// ---------------- one-time m split:  m -> 6 bf16 planes ----------------
__global__ void split_m_kernel(const float* __restrict__ mm) {
  long long i = (long long)blockIdx.x * 256 + threadIdx.x;   // over BB*NN*2*NE
  int j = (int)(i & 4095);
  long long bn = i >> 12;
  int n = (int)(bn & 511);
  int b = (int)(bn >> 9);
  int dir = j >> 11, k = j & 2047;
  float v = mm[i];
  __nv_bfloat16 p0, p1, p2;
  split3b(v, p0, p1, p2);
  g_mA[dir][b][0][n][k] = p0;
  g_mA[dir][b][1][n][k] = p1;
  g_mA[dir][b][2][n][k] = p2;
}

// ---------------- SIMT GEMM cores ----------------
// single-B (R2-proven) — used by gate_t
template <class ALoad, class BLoad, class Epi>
__device__ __forceinline__ void gemm64(ALoad aload, BLoad bload, Epi epi, int K) {
  __shared__ __align__(16) float As[16][68];
  __shared__ __align__(16) float Bs[16][64];
  float acc[4][4] = {};
  const int tid = threadIdx.x;
  const int tx = tid & 15, ty = tid >> 4;
  const int ar = tid >> 2, ak = (tid & 3) << 2;
  const int bk = tid >> 4, bn = (tid & 15) << 2;

  for (int k0 = 0; k0 < K; k0 += 16) {
    float4 av = aload(ar, k0 + ak);
    As[ak + 0][ar] = av.x;
    As[ak + 1][ar] = av.y;
    As[ak + 2][ar] = av.z;
    As[ak + 3][ar] = av.w;
    float4 bv = bload(k0 + bk, bn);
    *reinterpret_cast<float4*>(&Bs[bk][bn]) = bv;
    __syncthreads();
#pragma unroll
    for (int kk = 0; kk < 16; kk++) {
      float4 a4 = *reinterpret_cast<const float4*>(&As[kk][ty << 2]);
      float4 b4 = *reinterpret_cast<const float4*>(&Bs[kk][tx << 2]);
      float a[4] = {a4.x, a4.y, a4.z, a4.w};
      float b[4] = {b4.x, b4.y, b4.z, b4.w};
#pragma unroll
      for (int i = 0; i < 4; i++)
#pragma unroll
        for (int j = 0; j < 4; j++) acc[i][j] += a[i] * b[j];
    }
    __syncthreads();
  }
  epi(acc, ty, tx);
}

// dual-B: shared A, two weight streams, two accumulators (fused proj / fused z+r)
template <class ALoad, class BLoad0, class BLoad1, class Epi>
__device__ __forceinline__ void gemm64_dual(ALoad aload, BLoad0 bload0, BLoad1 bload1,
                                            Epi epi, int K) {
  __shared__ __align__(16) float As[16][68];
  __shared__ __align__(16) float B0s[16][64];
  __shared__ __align__(16) float B1s[16][64];
  float acc0[4][4] = {}, acc1[4][4] = {};
  const int tid = threadIdx.x;
  const int tx = tid & 15, ty = tid >> 4;
  const int ar = tid >> 2, ak = (tid & 3) << 2;
  const int bk = tid >> 4, bn = (tid & 15) << 2;

  for (int k0 = 0; k0 < K; k0 += 16) {
    float4 av = aload(ar, k0 + ak);
    As[ak + 0][ar] = av.x;
    As[ak + 1][ar] = av.y;
    As[ak + 2][ar] = av.z;
    As[ak + 3][ar] = av.w;
    float4 bv0 = bload0(k0 + bk, bn);
    *reinterpret_cast<float4*>(&B0s[bk][bn]) = bv0;
    float4 bv1 = bload1(k0 + bk, bn);
    *reinterpret_cast<float4*>(&B1s[bk][bn]) = bv1;
    __syncthreads();
#pragma unroll
    for (int kk = 0; kk < 16; kk++) {
      float4 a4 = *reinterpret_cast<const float4*>(&As[kk][ty << 2]);
      float4 b04 = *reinterpret_cast<const float4*>(&B0s[kk][tx << 2]);
      float4 b14 = *reinterpret_cast<const float4*>(&B1s[kk][tx << 2]);
      float a[4] = {a4.x, a4.y, a4.z, a4.w};
      float b0[4] = {b04.x, b04.y, b04.z, b04.w};
      float b1[4] = {b14.x, b14.y, b14.z, b14.w};
#pragma unroll
      for (int i = 0; i < 4; i++)
#pragma unroll
        for (int j = 0; j < 4; j++) {
          acc0[i][j] += a[i] * b0[j];
          acc1[i][j] += a[i] * b1[j];
        }
    }
    __syncthreads();
  }
  epi(acc0, acc1, ty, tx);
}

__global__ void copy_h_kernel(const float* __restrict__ x) {
  int i = blockIdx.x * 256 + threadIdx.x;
  g_h[i] = x[i];
}

// fused proj: y_in = h@W_in+b_in, y_out = h@W_out+b_out -> 3 bf16 planes each
__global__ void proj_fused(const float* __restrict__ Wi, const float* __restrict__ bi,
                           const float* __restrict__ Wo, const float* __restrict__ bo) {
  const int m0 = blockIdx.y << 6;
  const int n0 = blockIdx.x << 6;
  auto aload = [&](int r, int k) {
    return *reinterpret_cast<const float4*>(&g_h[(m0 + r) * HH + k]);
  };
  auto bload0 = [&](int k, int n) {
    return *reinterpret_cast<const float4*>(&Wi[k * (HH * EE) + n0 + n]);
  };
  auto bload1 = [&](int k, int n) {
    return *reinterpret_cast<const float4*>(&Wo[k * (HH * EE) + n0 + n]);
  };
  auto epi = [&](float (&a0)[4][4], float (&a1)[4][4], int ty, int tx) {
#pragma unroll
    for (int i = 0; i < 4; i++) {
      int row = m0 + (ty << 2) + i;
      int b = row >> 9, n = row & (NN - 1);
#pragma unroll
      for (int j = 0; j < 4; j++) {
        int col = n0 + (tx << 2) + j;
        int e = col & 3, hh = col >> 2;
        int mp = e * NN + n;
        __nv_bfloat16 p0, p1, p2;
        split3b(a0[i][j] + bi[col], p0, p1, p2);
        g_stB[0][b][0][mp][hh] = p0;
        g_stB[0][b][1][mp][hh] = p1;
        g_stB[0][b][2][mp][hh] = p2;
        split3b(a1[i][j] + bo[col], p0, p1, p2);
        g_stB[1][b][0][mp][hh] = p0;
        g_stB[1][b][1][mp][hh] = p1;
        g_stB[1][b][2][mp][hh] = p2;
      }
    }
  };
  gemm64_dual(aload, bload0, bload1, epi, HH);
}

// ---------------- einsum: cp.async + ldmatrix + 6-term bf16 MMA ----------------
// K = 2048 in 32 chunks of 64. 2-stage cp.async ring, ONE sync per chunk.
// 8 warps (4M x 2N), warp tile 32x64. Per fragment: 3 independent 2-deep chains.
#define A_ROWB 144                     /* bytes per A smem row (128 data + 16 pad) */
#define A_PLB  (128 * A_ROWB)          /* 18432 B */
#define B_ROWB 272                     /* bytes per B smem k-row (256 + 16 pad) */
#define B_PLB  (64 * B_ROWB)           /* 17408 B */
#define A_STB  (3 * A_PLB)             /* 55296 B */
#define STAGE_B (A_STB + 3 * B_PLB)    /* 107520 B */
#define EIN_SMEM (2 * STAGE_B)         /* 215040 B */

__global__ __launch_bounds__(256, 1) void einsum_cp() {
  extern __shared__ __align__(16) char sm[];
  const unsigned su = (unsigned)__cvta_generic_to_shared(sm);
  const int tid = threadIdx.x, lane = tid & 31, wid = tid >> 5;
  const int wm = (wid & 3) << 5;
  const int wn = (wid >> 2) << 6;

  const int zz = blockIdx.y, dir = zz & 1, b = zz >> 1;
  const int m0 = blockIdx.x << 7;
  const __nv_bfloat16* Ag = &g_mA[dir][b][0][0][0];
  const __nv_bfloat16* Bg = &g_stB[dir][b][0][0][0];

  auto copy = [&](int c, int s) {
    const unsigned sb = su + s * STAGE_B;
#pragma unroll
    for (int i = 0; i < 12; i++) {           // A: 3 planes x 128 rows x 8 segs
      int u = tid + (i << 8);
      int p = u >> 10, rem = u & 1023;
      int r = rem >> 3, seg = rem & 7;
      cpa16(sb + p * A_PLB + r * A_ROWB + seg * 16,
            Ag + (size_t)p * (NN * NE) + (size_t)(m0 + r) * NE + (c << 6) + seg * 8);
    }
#pragma unroll
    for (int i = 0; i < 12; i++) {           // B: 3 planes x 64 k-rows x 16 segs
      int u = tid + (i << 8);
      int p = u >> 10, rem = u & 1023;
      int r = rem >> 4, seg = rem & 15;
      cpa16(sb + A_STB + p * B_PLB + r * B_ROWB + seg * 16,
            Bg + (size_t)p * (NE * HH) + (size_t)((c << 6) + r) * HH + seg * 8);
    }
  };

  float acc[2][8][4] = {};

  copy(0, 0); CP_COMMIT();

  const int la = lane & 7, lb = (lane >> 3) & 1, lc = lane >> 4;

  for (int c = 0; c < 32; c++) {
    CP_WAIT0();
    __syncthreads();
    if (c + 1 < 32) { copy(c + 1, (c + 1) & 1); CP_COMMIT(); }

    const unsigned Ab = su + (c & 1) * STAGE_B;
    const unsigned Bb = Ab + A_STB;
#pragma unroll
    for (int ks = 0; ks < 4; ks++) {
      unsigned af[3][2][4];
#pragma unroll
      for (int p = 0; p < 3; p++)
#pragma unroll
        for (int mi = 0; mi < 2; mi++)
          ldm_x4(af[p][mi],
                 Ab + p * A_PLB + (wm + (mi << 4) + la + lb * 8) * A_ROWB + ks * 32 + lc * 16);

      unsigned bfr[3][8][2];
#pragma unroll
      for (int p = 0; p < 3; p++)
#pragma unroll
        for (int g4 = 0; g4 < 4; g4++)
          ldm_x4t(bfr[p][2 * g4][0], bfr[p][2 * g4][1],
                  bfr[p][2 * g4 + 1][0], bfr[p][2 * g4 + 1][1],
                  Bb + p * B_PLB + ((ks << 4) + la + lb * 8) * B_ROWB +
                      (wn + (g4 << 4) + lc * 8) * 2);

#pragma unroll
      for (int nj = 0; nj < 8; nj++)
#pragma unroll
        for (int mi = 0; mi < 2; mi++) {
          // 3 independent 2-deep chains (smallest-first within each), RN folds.
          float pa[4] = {0.f, 0.f, 0.f, 0.f};
          float pb[4] = {0.f, 0.f, 0.f, 0.f};
          float pc[4] = {0.f, 0.f, 0.f, 0.f};
          mma16(pa, af[2][mi], bfr[0][nj][0], bfr[0][nj][1]);   // A2*B0
          mma16(pb, af[1][mi], bfr[1][nj][0], bfr[1][nj][1]);   // A1*B1
          mma16(pc, af[0][mi], bfr[2][nj][0], bfr[2][nj][1]);   // A0*B2
          mma16(pa, af[1][mi], bfr[0][nj][0], bfr[0][nj][1]);   // A1*B0
          mma16(pb, af[0][mi], bfr[1][nj][0], bfr[1][nj][1]);   // A0*B1
          mma16(pc, af[0][mi], bfr[0][nj][0], bfr[0][nj][1]);   // A0*B0
#pragma unroll
          for (int q = 0; q < 4; q++) acc[mi][nj][q] += pa[q];
#pragma unroll
          for (int q = 0; q < 4; q++) acc[mi][nj][q] += pb[q];
#pragma unroll
          for (int q = 0; q < 4; q++) acc[mi][nj][q] += pc[q];
        }
    }
  }

  float* Cb = (dir ? g_aout : g_ain) + (size_t)(b * NN + m0) * HH;
  const int qr = lane >> 2, qc = lane & 3;
#pragma unroll
  for (int mi = 0; mi < 2; mi++)
#pragma unroll
    for (int nj = 0; nj < 8; nj++) {
      int r = wm + (mi << 4) + qr;
      int cc = wn + (nj << 3) + (qc << 1);
      *reinterpret_cast<float2*>(&Cb[r * HH + cc]) =
          make_float2(acc[mi][nj][0], acc[mi][nj][1]);
      *reinterpret_cast<float2*>(&Cb[(r + 8) * HH + cc]) =
          make_float2(acc[mi][nj][2], acc[mi][nj][3]);
    }
}

// fused z+r gate: A = [a_in|a_out|h]; z = sigmoid(.), rh = sigmoid(.)*h
__global__ void gate_zr(const float* __restrict__ Wz, const float* __restrict__ bz,
                        const float* __restrict__ Wr, const float* __restrict__ br) {
  const int m0 = blockIdx.y << 6;
  const int n0 = blockIdx.x << 6;
  auto aload = [&](int r, int k) -> float4 {
    int row = m0 + r;
    const float* base;
    if (k < 128)       base = &g_ain[row * HH + k];
    else if (k < 256)  base = &g_aout[row * HH + (k - 128)];
    else               base = &g_h[row * HH + (k - 256)];
    return *reinterpret_cast<const float4*>(base);
  };
  auto bload0 = [&](int k, int n) {
    return *reinterpret_cast<const float4*>(&Wz[k * HH + n0 + n]);
  };
  auto bload1 = [&](int k, int n) {
    return *reinterpret_cast<const float4*>(&Wr[k * HH + n0 + n]);
  };
  auto epi = [&](float (&a0)[4][4], float (&a1)[4][4], int ty, int tx) {
#pragma unroll
    for (int i = 0; i < 4; i++) {
      int row = m0 + (ty << 2) + i;
#pragma unroll
      for (int j = 0; j < 4; j++) {
        int col = n0 + (tx << 2) + j;
        int idx = row * HH + col;
        g_z[idx] = sigmoidf_(a0[i][j] + bz[col]);
        g_rh[idx] = sigmoidf_(a1[i][j] + br[col]) * g_h[idx];
      }
    }
  };
  gemm64_dual(aload, bload0, bload1, epi, 3 * HH);
}

// t gate: h = (1-z)*h + z*tanh([a_in|a_out|rh] @ W_t + b_t)
__global__ void gate_t(const float* __restrict__ W, const float* __restrict__ bias) {
  const int m0 = blockIdx.y << 6;
  const int n0 = blockIdx.x << 6;
  auto aload = [&](int r, int k) -> float4 {
    int row = m0 + r;
    const float* base;
    if (k < 128)       base = &g_ain[row * HH + k];
    else if (k < 256)  base = &g_aout[row * HH + (k - 128)];
    else               base = &g_rh[row * HH + (k - 256)];
    return *reinterpret_cast<const float4*>(base);
  };
  auto bload = [&](int k, int n) {
    return *reinterpret_cast<const float4*>(&W[k * HH + n0 + n]);
  };
  auto epi = [&](float (&acc)[4][4], int ty, int tx) {
#pragma unroll
    for (int i = 0; i < 4; i++) {
      int row = m0 + (ty << 2) + i;
#pragma unroll
      for (int j = 0; j < 4; j++) {
        int col = n0 + (tx << 2) + j;
        int idx = row * HH + col;
        float t = tanhf(acc[i][j] + bias[col]);
        float z = g_z[idx];
        g_h[idx] = (1.0f - z) * g_h[idx] + z * t;
      }
    }
  };
  gemm64(aload, bload, epi, 3 * HH);
}

__global__ void final_kernel(const float* __restrict__ a,
                             const float* __restrict__ W1,
                             const float* __restrict__ b1,
                             const float* __restrict__ W2,
                             const float* __restrict__ b2,
                             float* __restrict__ out) {
  const int row = blockIdx.x;
  const int j = threadIdx.x;
  __shared__ float sh[HH + 1];
  __shared__ float red[HH];
  sh[j] = g_h[row * HH + j];
  if (j == 0) sh[HH] = a[row];
  __syncthreads();
  float acc = b1[j];
#pragma unroll 4
  for (int k = 0; k < HH + 1; k++) acc += sh[k] * W1[k * HH + j];
  red[j] = tanhf(acc) * W2[j];
  __syncthreads();
  for (int s = 64; s > 0; s >>= 1) {
    if (j < s) red[j] += red[j + s];
    __syncthreads();
  }
  if (j == 0) out[row] = red[0] + b2[0];
}

// ---------------- launch ----------------
extern "C" void kernel_launch(void* const* d_in, const int* in_sizes, int n_in,
                              void* d_out, int out_size) {
  const float* x     = (const float*)d_in[0];
  const float* a     = (const float*)d_in[1];
  const float* m     = (const float*)d_in[2];
  const float* W_in  = (const float*)d_in[3];
  const float* b_in  = (const float*)d_in[4];
  const float* W_out = (const float*)d_in[5];
  const float* b_out = (const float*)d_in[6];
  const float* W_z   = (const float*)d_in[7];
  const float* b_z   = (const float*)d_in[8];
  const float* W_r   = (const float*)d_in[9];
  const float* b_r   = (const float*)d_in[10];
  const float* W_t   = (const float*)d_in[11];
  const float* b_t   = (const float*)d_in[12];
  const float* W1    = (const float*)d_in[13];
  const float* b1    = (const float*)d_in[14];
  const float* W2    = (const float*)d_in[15];
  const float* b2    = (const float*)d_in[16];
  float* out = (float*)d_out;

  cudaFuncSetAttribute(einsum_cp, cudaFuncAttributeMaxDynamicSharedMemorySize, EIN_SMEM);

  copy_h_kernel<<<NR * HH / 256, 256>>>(x);
  split_m_kernel<<<(BB * NN * 2 * NE) / 256, 256>>>(m);

  dim3 gp(8, 128);       // proj_fused: 512/64 x 8192/64
  dim3 ge(4, 2 * BB);    // einsum:     512/128 x (b,dir)
  dim3 gg(2, 128);       // gates:      128/64 x 8192/64

  for (int s = 0; s < STEPS; s++) {
    proj_fused<<<gp, 256>>>(W_in, b_in, W_out, b_out);
    einsum_cp<<<ge, 256, EIN_SMEM>>>();
    gate_zr<<<gg, 256>>>(W_z, b_z, W_r, b_r);
    gate_t<<<gg, 256>>>(W_t, b_t);
  }

  final_kernel<<<NR, 128>>>(a, W1, b1, W2, b2, out);
}

// round 16
// speedup vs baseline: 1.6482x; 1.2012x over previous
#include <cuda_runtime.h>
#include <cuda_fp16.h>
#include <math.h>

#define BB 16
#define NN 512
#define HH 128
#define EE 4
#define NE 2048          /* NN*EE */
#define NR 8192          /* BB*NN */
#define STEPS 5

// lo-plane scale: residuals (~2^-12) stored x2048 -> normal fp16 range
#define LSCALE 2048.0f
#define C11 4.8828125e-4f            /* 2^-11 */
#define C22 2.384185791015625e-7f    /* 2^-22 */

// ---------------- scratch (device globals; no allocation) ----------------
__device__ float g_h[NR * HH];
__device__ float g_ain[NR * HH];
__device__ float g_aout[NR * HH];
__device__ float g_z[NR * HH];
__device__ float g_rh[NR * HH];
// fp16 split planes: x = p0 + p1/2048 (Dekker; p1 stored scaled, always normal)
__device__ __half g_mA[2][BB][2][NN][NE];    // m planes [dir][b][p][n'][k]
__device__ __half g_stB[2][BB][2][NE][HH];   // state planes [dir][b][p][m'][h]

__device__ __forceinline__ float sigmoidf_(float v) { return 1.0f / (1.0f + expf(-v)); }

__device__ __forceinline__ void split2hs(float x, __half& h0, __half& h1s) {
  h0 = __float2half_rn(x);
  float r = x - __half2float(h0);
  h1s = __float2half_rn(r * LSCALE);
}

// ---------------- PTX helpers (baseline sm_80+, legal on compute_103) ----
__device__ __forceinline__ void mma16(float (&d)[4], const unsigned (&a)[4],
                                      unsigned b0, unsigned b1) {
  asm volatile(
      "mma.sync.aligned.m16n8k16.row.col.f32.f16.f16.f32 "
      "{%0,%1,%2,%3}, {%4,%5,%6,%7}, {%8,%9}, {%0,%1,%2,%3};"
      : "+f"(d[0]), "+f"(d[1]), "+f"(d[2]), "+f"(d[3])
      : "r"(a[0]), "r"(a[1]), "r"(a[2]), "r"(a[3]), "r"(b0), "r"(b1));
}
__device__ __forceinline__ void ldm_x4(unsigned* r, unsigned addr) {
  asm volatile("ldmatrix.sync.aligned.m8n8.x4.shared.b16 {%0,%1,%2,%3}, [%4];"
               : "=r"(r[0]), "=r"(r[1]), "=r"(r[2]), "=r"(r[3]) : "r"(addr));
}
__device__ __forceinline__ void ldm_x4t(unsigned& r0, unsigned& r1, unsigned& r2,
                                        unsigned& r3, unsigned addr) {
  asm volatile("ldmatrix.sync.aligned.m8n8.x4.trans.shared.b16 {%0,%1,%2,%3}, [%4];"
               : "=r"(r0), "=r"(r1), "=r"(r2), "=r"(r3) : "r"(addr));
}
__device__ __forceinline__ void cpa16(unsigned dst, const void* src) {
  asm volatile("cp.async.cg.shared.global [%0], [%1], 16;" :: "r"(dst), "l"(src));
}
#define CP_COMMIT() asm volatile("cp.async.commit_group;" ::: "memory")
#define CP_WAIT0()  asm volatile("cp.async.wait_group 0;" ::: "memory")

// ---------------- one-time m split:  m -> 4 fp16 planes ----------------
__global__ void split_m_kernel(const float* __restrict__ mm) {
  long long i = (long long)blockIdx.x * 256 + threadIdx.x;   // over BB*NN*2*NE
  int j = (int)(i & 4095);
  long long bn = i >> 12;
  int n = (int)(bn & 511);
  int b = (int)(bn >> 9);
  int dir = j >> 11, k = j & 2047;
  float v = mm[i];
  __half p0, p1;
  split2hs(v, p0, p1);
  g_mA[dir][b][0][n][k] = p0;
  g_mA[dir][b][1][n][k] = p1;
}

// ---------------- SIMT GEMM cores ----------------
template <class ALoad, class BLoad, class Epi>
__device__ __forceinline__ void gemm64(ALoad aload, BLoad bload, Epi epi, int K) {
  __shared__ __align__(16) float As[16][68];
  __shared__ __align__(16) float Bs[16][64];
  float acc[4][4] = {};
  const int tid = threadIdx.x;
  const int tx = tid & 15, ty = tid >> 4;
  const int ar = tid >> 2, ak = (tid & 3) << 2;
  const int bk = tid >> 4, bn = (tid & 15) << 2;

  for (int k0 = 0; k0 < K; k0 += 16) {
    float4 av = aload(ar, k0 + ak);
    As[ak + 0][ar] = av.x;
    As[ak + 1][ar] = av.y;
    As[ak + 2][ar] = av.z;
    As[ak + 3][ar] = av.w;
    float4 bv = bload(k0 + bk, bn);
    *reinterpret_cast<float4*>(&Bs[bk][bn]) = bv;
    __syncthreads();
#pragma unroll
    for (int kk = 0; kk < 16; kk++) {
      float4 a4 = *reinterpret_cast<const float4*>(&As[kk][ty << 2]);
      float4 b4 = *reinterpret_cast<const float4*>(&Bs[kk][tx << 2]);
      float a[4] = {a4.x, a4.y, a4.z, a4.w};
      float b[4] = {b4.x, b4.y, b4.z, b4.w};
#pragma unroll
      for (int i = 0; i < 4; i++)
#pragma unroll
        for (int j = 0; j < 4; j++) acc[i][j] += a[i] * b[j];
    }
    __syncthreads();
  }
  epi(acc, ty, tx);
}

template <class ALoad, class BLoad0, class BLoad1, class Epi>
__device__ __forceinline__ void gemm64_dual(ALoad aload, BLoad0 bload0, BLoad1 bload1,
                                            Epi epi, int K) {
  __shared__ __align__(16) float As[16][68];
  __shared__ __align__(16) float B0s[16][64];
  __shared__ __align__(16) float B1s[16][64];
  float acc0[4][4] = {}, acc1[4][4] = {};
  const int tid = threadIdx.x;
  const int tx = tid & 15, ty = tid >> 4;
  const int ar = tid >> 2, ak = (tid & 3) << 2;
  const int bk = tid >> 4, bn = (tid & 15) << 2;

  for (int k0 = 0; k0 < K; k0 += 16) {
    float4 av = aload(ar, k0 + ak);
    As[ak + 0][ar] = av.x;
    As[ak + 1][ar] = av.y;
    As[ak + 2][ar] = av.z;
    As[ak + 3][ar] = av.w;
    float4 bv0 = bload0(k0 + bk, bn);
    *reinterpret_cast<float4*>(&B0s[bk][bn]) = bv0;
    float4 bv1 = bload1(k0 + bk, bn);
    *reinterpret_cast<float4*>(&B1s[bk][bn]) = bv1;
    __syncthreads();
#pragma unroll
    for (int kk = 0; kk < 16; kk++) {
      float4 a4 = *reinterpret_cast<const float4*>(&As[kk][ty << 2]);
      float4 b04 = *reinterpret_cast<const float4*>(&B0s[kk][tx << 2]);
      float4 b14 = *reinterpret_cast<const float4*>(&B1s[kk][tx << 2]);
      float a[4] = {a4.x, a4.y, a4.z, a4.w};
      float b0[4] = {b04.x, b04.y, b04.z, b04.w};
      float b1[4] = {b14.x, b14.y, b14.z, b14.w};
#pragma unroll
      for (int i = 0; i < 4; i++)
#pragma unroll
        for (int j = 0; j < 4; j++) {
          acc0[i][j] += a[i] * b0[j];
          acc1[i][j] += a[i] * b1[j];
        }
    }
    __syncthreads();
  }
  epi(acc0, acc1, ty, tx);
}

__global__ void copy_h_kernel(const float* __restrict__ x) {
  int i = blockIdx.x * 256 + threadIdx.x;
  g_h[i] = x[i];
}

// fused proj: y_in = h@W_in+b_in, y_out = h@W_out+b_out -> 2 fp16 planes each
__global__ void proj_fused(const float* __restrict__ Wi, const float* __restrict__ bi,
                           const float* __restrict__ Wo, const float* __restrict__ bo) {
  const int m0 = blockIdx.y << 6;
  const int n0 = blockIdx.x << 6;
  auto aload = [&](int r, int k) {
    return *reinterpret_cast<const float4*>(&g_h[(m0 + r) * HH + k]);
  };
  auto bload0 = [&](int k, int n) {
    return *reinterpret_cast<const float4*>(&Wi[k * (HH * EE) + n0 + n]);
  };
  auto bload1 = [&](int k, int n) {
    return *reinterpret_cast<const float4*>(&Wo[k * (HH * EE) + n0 + n]);
  };
  auto epi = [&](float (&a0)[4][4], float (&a1)[4][4], int ty, int tx) {
#pragma unroll
    for (int i = 0; i < 4; i++) {
      int row = m0 + (ty << 2) + i;
      int b = row >> 9, n = row & (NN - 1);
#pragma unroll
      for (int j = 0; j < 4; j++) {
        int col = n0 + (tx << 2) + j;
        int e = col & 3, hh = col >> 2;
        int mp = e * NN + n;
        __half p0, p1;
        split2hs(a0[i][j] + bi[col], p0, p1);
        g_stB[0][b][0][mp][hh] = p0;
        g_stB[0][b][1][mp][hh] = p1;
        split2hs(a1[i][j] + bo[col], p0, p1);
        g_stB[1][b][0][mp][hh] = p0;
        g_stB[1][b][1][mp][hh] = p1;
      }
    }
  };
  gemm64_dual(aload, bload0, bload1, epi, HH);
}

// ---------------- einsum: cp.async + ldmatrix + 4-term fp16 MMA ----------------
// K = 2048 in 32 chunks of 64. 2-stage cp.async ring, ONE sync per chunk.
// 8 warps (4M x 2N), warp tile 32x64. Per fragment: 3 partial chains (depth<=2),
// folded with exact power-of-2 rescales: acc += p11*2^-22 + px*2^-11 + p00.
#define A_ROWB 144                     /* bytes per A smem row (128 data + 16 pad) */
#define A_PLB  (128 * A_ROWB)          /* 18432 B */
#define B_ROWB 272                     /* bytes per B smem k-row (256 + 16 pad) */
#define B_PLB  (64 * B_ROWB)           /* 17408 B */
#define A_STB  (2 * A_PLB)             /* 36864 B */
#define STAGE_B (A_STB + 2 * B_PLB)    /* 71680 B */
#define EIN_SMEM (2 * STAGE_B)         /* 143360 B */

__global__ __launch_bounds__(256, 1) void einsum_cp() {
  extern __shared__ __align__(16) char sm[];
  const unsigned su = (unsigned)__cvta_generic_to_shared(sm);
  const int tid = threadIdx.x, lane = tid & 31, wid = tid >> 5;
  const int wm = (wid & 3) << 5;
  const int wn = (wid >> 2) << 6;

  const int zz = blockIdx.y, dir = zz & 1, b = zz >> 1;
  const int m0 = blockIdx.x << 7;
  const __half* Ag = &g_mA[dir][b][0][0][0];   // plane stride NN*NE
  const __half* Bg = &g_stB[dir][b][0][0][0];  // plane stride NE*HH

  auto copy = [&](int c, int s) {
    const unsigned sb = su + s * STAGE_B;
#pragma unroll
    for (int i = 0; i < 8; i++) {            // A: 2 planes x 128 rows x 8 segs
      int u = tid + (i << 8);
      int p = u >> 10, rem = u & 1023;
      int r = rem >> 3, seg = rem & 7;
      cpa16(sb + p * A_PLB + r * A_ROWB + seg * 16,
            Ag + (size_t)p * (NN * NE) + (size_t)(m0 + r) * NE + (c << 6) + seg * 8);
    }
#pragma unroll
    for (int i = 0; i < 8; i++) {            // B: 2 planes x 64 k-rows x 16 segs
      int u = tid + (i << 8);
      int p = u >> 10, rem = u & 1023;
      int r = rem >> 4, seg = rem & 15;
      cpa16(sb + A_STB + p * B_PLB + r * B_ROWB + seg * 16,
            Bg + (size_t)p * (NE * HH) + (size_t)((c << 6) + r) * HH + seg * 8);
    }
  };

  float acc[2][8][4] = {};

  copy(0, 0); CP_COMMIT();

  const int la = lane & 7, lb = (lane >> 3) & 1, lc = lane >> 4;

  for (int c = 0; c < 32; c++) {
    CP_WAIT0();
    __syncthreads();
    if (c + 1 < 32) { copy(c + 1, (c + 1) & 1); CP_COMMIT(); }

    const unsigned Ab = su + (c & 1) * STAGE_B;
    const unsigned Bb = Ab + A_STB;
#pragma unroll
    for (int ks = 0; ks < 4; ks++) {
      unsigned af[2][2][4];
#pragma unroll
      for (int p = 0; p < 2; p++)
#pragma unroll
        for (int mi = 0; mi < 2; mi++)
          ldm_x4(af[p][mi],
                 Ab + p * A_PLB + (wm + (mi << 4) + la + lb * 8) * A_ROWB + ks * 32 + lc * 16);

      unsigned bfr[2][8][2];
#pragma unroll
      for (int p = 0; p < 2; p++)
#pragma unroll
        for (int g4 = 0; g4 < 4; g4++)
          ldm_x4t(bfr[p][2 * g4][0], bfr[p][2 * g4][1],
                  bfr[p][2 * g4 + 1][0], bfr[p][2 * g4 + 1][1],
                  Bb + p * B_PLB + ((ks << 4) + la + lb * 8) * B_ROWB +
                      (wn + (g4 << 4) + lc * 8) * 2);

#pragma unroll
      for (int nj = 0; nj < 8; nj++)
#pragma unroll
        for (int mi = 0; mi < 2; mi++) {
          float p00[4] = {0.f, 0.f, 0.f, 0.f};
          float px[4]  = {0.f, 0.f, 0.f, 0.f};
          float p11[4] = {0.f, 0.f, 0.f, 0.f};
          mma16(p11, af[1][mi], bfr[1][nj][0], bfr[1][nj][1]);   // A1'*B1'
          mma16(px,  af[1][mi], bfr[0][nj][0], bfr[0][nj][1]);   // A1'*B0
          mma16(p00, af[0][mi], bfr[0][nj][0], bfr[0][nj][1]);   // A0*B0
          mma16(px,  af[0][mi], bfr[1][nj][0], bfr[1][nj][1]);   // A0*B1'
#pragma unroll
          for (int q = 0; q < 4; q++) {
            float a = acc[mi][nj][q];
            a = fmaf(p11[q], C22, a);
            a = fmaf(px[q],  C11, a);
            acc[mi][nj][q] = a + p00[q];
          }
        }
    }
  }

  float* Cb = (dir ? g_aout : g_ain) + (size_t)(b * NN + m0) * HH;
  const int qr = lane >> 2, qc = lane & 3;
#pragma unroll
  for (int mi = 0; mi < 2; mi++)
#pragma unroll
    for (int nj = 0; nj < 8; nj++) {
      int r = wm + (mi << 4) + qr;
      int cc = wn + (nj << 3) + (qc << 1);
      *reinterpret_cast<float2*>(&Cb[r * HH + cc]) =
          make_float2(acc[mi][nj][0], acc[mi][nj][1]);
      *reinterpret_cast<float2*>(&Cb[(r + 8) * HH + cc]) =
          make_float2(acc[mi][nj][2], acc[mi][nj][3]);
    }
}

// fused z+r gate
__global__ void gate_zr(const float* __restrict__ Wz, const float* __restrict__ bz,
                        const float* __restrict__ Wr, const float* __restrict__ br) {
  const int m0 = blockIdx.y << 6;
  const int n0 = blockIdx.x << 6;
  auto aload = [&](int r, int k) -> float4 {
    int row = m0 + r;
    const float* base;
    if (k < 128)       base = &g_ain[row * HH + k];
    else if (k < 256)  base = &g_aout[row * HH + (k - 128)];
    else               base = &g_h[row * HH + (k - 256)];
    return *reinterpret_cast<const float4*>(base);
  };
  auto bload0 = [&](int k, int n) {
    return *reinterpret_cast<const float4*>(&Wz[k * HH + n0 + n]);
  };
  auto bload1 = [&](int k, int n) {
    return *reinterpret_cast<const float4*>(&Wr[k * HH + n0 + n]);
  };
  auto epi = [&](float (&a0)[4][4], float (&a1)[4][4], int ty, int tx) {
#pragma unroll
    for (int i = 0; i < 4; i++) {
      int row = m0 + (ty << 2) + i;
#pragma unroll
      for (int j = 0; j < 4; j++) {
        int col = n0 + (tx << 2) + j;
        int idx = row * HH + col;
        g_z[idx] = sigmoidf_(a0[i][j] + bz[col]);
        g_rh[idx] = sigmoidf_(a1[i][j] + br[col]) * g_h[idx];
      }
    }
  };
  gemm64_dual(aload, bload0, bload1, epi, 3 * HH);
}

// t gate
__global__ void gate_t(const float* __restrict__ W, const float* __restrict__ bias) {
  const int m0 = blockIdx.y << 6;
  const int n0 = blockIdx.x << 6;
  auto aload = [&](int r, int k) -> float4 {
    int row = m0 + r;
    const float* base;
    if (k < 128)       base = &g_ain[row * HH + k];
    else if (k < 256)  base = &g_aout[row * HH + (k - 128)];
    else               base = &g_rh[row * HH + (k - 256)];
    return *reinterpret_cast<const float4*>(base);
  };
  auto bload = [&](int k, int n) {
    return *reinterpret_cast<const float4*>(&W[k * HH + n0 + n]);
  };
  auto epi = [&](float (&acc)[4][4], int ty, int tx) {
#pragma unroll
    for (int i = 0; i < 4; i++) {
      int row = m0 + (ty << 2) + i;
#pragma unroll
      for (int j = 0; j < 4; j++) {
        int col = n0 + (tx << 2) + j;
        int idx = row * HH + col;
        float t = tanhf(acc[i][j] + bias[col]);
        float z = g_z[idx];
        g_h[idx] = (1.0f - z) * g_h[idx] + z * t;
      }
    }
  };
  gemm64(aload, bload, epi, 3 * HH);
}

__global__ void final_kernel(const float* __restrict__ a,
                             const float* __restrict__ W1,
                             const float* __restrict__ b1,
                             const float* __restrict__ W2,
                             const float* __restrict__ b2,
                             float* __restrict__ out) {
  const int row = blockIdx.x;
  const int j = threadIdx.x;
  __shared__ float sh[HH + 1];
  __shared__ float red[HH];
  sh[j] = g_h[row * HH + j];
  if (j == 0) sh[HH] = a[row];
  __syncthreads();
  float acc = b1[j];
#pragma unroll 4
  for (int k = 0; k < HH + 1; k++) acc += sh[k] * W1[k * HH + j];
  red[j] = tanhf(acc) * W2[j];
  __syncthreads();
  for (int s = 64; s > 0; s >>= 1) {
    if (j < s) red[j] += red[j + s];
    __syncthreads();
  }
  if (j == 0) out[row] = red[0] + b2[0];
}

// ---------------- launch ----------------
extern "C" void kernel_launch(void* const* d_in, const int* in_sizes, int n_in,
                              void* d_out, int out_size) {
  const float* x     = (const float*)d_in[0];
  const float* a     = (const float*)d_in[1];
  const float* m     = (const float*)d_in[2];
  const float* W_in  = (const float*)d_in[3];
  const float* b_in  = (const float*)d_in[4];
  const float* W_out = (const float*)d_in[5];
  const float* b_out = (const float*)d_in[6];
  const float* W_z   = (const float*)d_in[7];
  const float* b_z   = (const float*)d_in[8];
  const float* W_r   = (const float*)d_in[9];
  const float* b_r   = (const float*)d_in[10];
  const float* W_t   = (const float*)d_in[11];
  const float* b_t   = (const float*)d_in[12];
  const float* W1    = (const float*)d_in[13];
  const float* b1    = (const float*)d_in[14];
  const float* W2    = (const float*)d_in[15];
  const float* b2    = (const float*)d_in[16];
  float* out = (float*)d_out;

  cudaFuncSetAttribute(einsum_cp, cudaFuncAttributeMaxDynamicSharedMemorySize, EIN_SMEM);

  copy_h_kernel<<<NR * HH / 256, 256>>>(x);
  split_m_kernel<<<(BB * NN * 2 * NE) / 256, 256>>>(m);

  dim3 gp(8, 128);       // proj_fused: 512/64 x 8192/64
  dim3 ge(4, 2 * BB);    // einsum:     512/128 x (b,dir)
  dim3 gg(2, 128);       // gates:      128/64 x 8192/64

  for (int s = 0; s < STEPS; s++) {
    proj_fused<<<gp, 256>>>(W_in, b_in, W_out, b_out);
    einsum_cp<<<ge, 256, EIN_SMEM>>>();
    gate_zr<<<gg, 256>>>(W_z, b_z, W_r, b_r);
    gate_t<<<gg, 256>>>(W_t, b_t);
  }

  final_kernel<<<NR, 128>>>(a, W1, b1, W2, b2, out);
}